// round 3
// baseline (speedup 1.0000x reference)
#include <cuda_runtime.h>
#include <cuda_bf16.h>
#include <cstdint>
#include <cstddef>

#define TT 8
#define MM 16384
#define KK 128
#define NN 1024

#define BM 128
#define BN 128
#define M_ITERS 8
#define MGROUPS 16          /* 16384 / 128 / 8 */

/* SMEM tiles: 128 rows x 136 bf16 (272 B pitch; pad keeps ldmatrix conflict-free) */
#define TPITCH     272
#define TILE_BYTES (128 * TPITCH)     /* 34816 */

#define SM_BIAS  0
#define SM_WHI   512
#define SM_WLO   (SM_WHI + TILE_BYTES)
#define SM_AHI   (SM_WLO + TILE_BYTES)
#define SM_ALO   (SM_AHI + TILE_BYTES)
#define SM_TOTAL (SM_ALO + TILE_BYTES)      /* 139776 B */
#define SM_STAGE SM_AHI                     /* fp32 stage reuses dead A region */
#define STAGE_LD 132                        /* fp32 row stride, 528 B, 16B-aligned */

/* ---- scratch (alloc-free rule: __device__ globals) ---- */
__device__ __align__(16) __nv_bfloat16 g_Ahi[(size_t)TT*MM*KK];
__device__ __align__(16) __nv_bfloat16 g_Alo[(size_t)TT*MM*KK];
__device__ __align__(16) __nv_bfloat16 g_Whi[(size_t)TT*NN*KK];
__device__ __align__(16) __nv_bfloat16 g_Wlo[(size_t)TT*NN*KK];

/* ============================ PTX helpers (all sm_80-era, legal on sm_103) ==== */
__device__ __forceinline__ uint32_t smem_u32(const void* p) {
    uint32_t a;
    asm("{ .reg .u64 t; cvta.to.shared.u64 t, %1; cvt.u32.u64 %0, t; }" : "=r"(a) : "l"(p));
    return a;
}
__device__ __forceinline__ void cp16(uint32_t s, const void* g) {
    asm volatile("cp.async.cg.shared.global [%0], [%1], 16;" :: "r"(s), "l"(g));
}
__device__ __forceinline__ void cp_wait_all() {
    asm volatile("cp.async.wait_all;" ::: "memory");
}
__device__ __forceinline__ void ldsm4(uint32_t* r, uint32_t addr) {
    asm volatile("ldmatrix.sync.aligned.m8n8.x4.shared.b16 {%0,%1,%2,%3}, [%4];"
                 : "=r"(r[0]), "=r"(r[1]), "=r"(r[2]), "=r"(r[3]) : "r"(addr));
}
__device__ __forceinline__ void mma16816(float* c, const uint32_t* a, const uint32_t* b) {
    asm volatile(
        "mma.sync.aligned.m16n8k16.row.col.f32.bf16.bf16.f32 "
        "{%0,%1,%2,%3}, {%4,%5,%6,%7}, {%8,%9}, {%0,%1,%2,%3};"
        : "+f"(c[0]), "+f"(c[1]), "+f"(c[2]), "+f"(c[3])
        : "r"(a[0]), "r"(a[1]), "r"(a[2]), "r"(a[3]), "r"(b[0]), "r"(b[1]));
}

/* ============================ split kernels ============================ */
__global__ void split_A_kernel(const float* __restrict__ A) {
    size_t i = (size_t)blockIdx.x * blockDim.x + threadIdx.x;   /* over float4s */
    float4 v = reinterpret_cast<const float4*>(A)[i];
    __nv_bfloat16 h0 = __float2bfloat16(v.x);
    __nv_bfloat16 h1 = __float2bfloat16(v.y);
    __nv_bfloat16 h2 = __float2bfloat16(v.z);
    __nv_bfloat16 h3 = __float2bfloat16(v.w);
    __nv_bfloat16 l0 = __float2bfloat16(v.x - __bfloat162float(h0));
    __nv_bfloat16 l1 = __float2bfloat16(v.y - __bfloat162float(h1));
    __nv_bfloat16 l2 = __float2bfloat16(v.z - __bfloat162float(h2));
    __nv_bfloat16 l3 = __float2bfloat16(v.w - __bfloat162float(h3));
    uint2 H, L;
    H.x = (uint32_t)__bfloat16_as_ushort(h0) | ((uint32_t)__bfloat16_as_ushort(h1) << 16);
    H.y = (uint32_t)__bfloat16_as_ushort(h2) | ((uint32_t)__bfloat16_as_ushort(h3) << 16);
    L.x = (uint32_t)__bfloat16_as_ushort(l0) | ((uint32_t)__bfloat16_as_ushort(l1) << 16);
    L.y = (uint32_t)__bfloat16_as_ushort(l2) | ((uint32_t)__bfloat16_as_ushort(l3) << 16);
    reinterpret_cast<uint2*>(g_Ahi)[i] = H;
    reinterpret_cast<uint2*>(g_Alo)[i] = L;
}

/* W [T,K,N] fp32 -> Whi/Wlo [T,N,K] bf16 (transposed: B operand wants [N,K] K-major) */
__global__ void split_W_kernel(const float* __restrict__ W) {
    int i = blockIdx.x * blockDim.x + threadIdx.x;       /* over T*K*N, n fastest */
    int n = i % NN;
    int k = (i / NN) % KK;
    int t = i / (NN * KK);
    float w = W[i];
    __nv_bfloat16 h = __float2bfloat16(w);
    float l = w - __bfloat162float(h);
    size_t o = ((size_t)(t * NN + n)) * KK + k;
    g_Whi[o] = h;
    g_Wlo[o] = __float2bfloat16(l);
}

/* ============================ main GEMM ============================ */
/* async-copy a 128x128 bf16 tile (gmem row stride 256 B) into padded smem rows */
__device__ __forceinline__ void load_tile_async(uint32_t sbase,
                                                const __nv_bfloat16* __restrict__ gsrc,
                                                int tid) {
    const char* g = reinterpret_cast<const char*>(gsrc);
    #pragma unroll
    for (int it = 0; it < 8; it++) {
        int c = tid + it * 256;                 /* 2048 16B chunks */
        int row = c >> 4, cc = c & 15;
        cp16(sbase + row * TPITCH + cc * 16, g + row * 256 + cc * 16);
    }
}

__global__ void __launch_bounds__(256, 1)
fused_gemm_kernel(const float* __restrict__ biases, float* __restrict__ out) {
    extern __shared__ char smem[];
    const uint32_t sb = smem_u32(smem);
    const int tid = threadIdx.x, wid = tid >> 5, lane = tid & 31;
    const int wm = wid & 1;          /* 2 warp-rows   (64 rows each) */
    const int wn = wid >> 1;         /* 4 warp-cols   (32 cols each) */
    const int n0 = blockIdx.y * BN;
    const int t  = blockIdx.z;

    if (tid < BN)
        reinterpret_cast<float*>(smem + SM_BIAS)[tid] = biases[t * NN + n0 + tid];

    /* W tiles resident for the whole CTA */
    load_tile_async(sb + SM_WHI, g_Whi + ((size_t)(t * NN + n0)) * KK, tid);
    load_tile_async(sb + SM_WLO, g_Wlo + ((size_t)(t * NN + n0)) * KK, tid);

    /* lane-dependent ldmatrix offsets */
    const uint32_t aLane = (uint32_t)((lane & 15) * TPITCH + ((lane & 16) ? 16 : 0));
    const uint32_t bLane = (uint32_t)(((lane & 7) + ((lane & 16) >> 1)) * TPITCH
                                      + (lane & 8) * 2);
    const uint32_t aHi = sb + SM_AHI + (wm * 64) * TPITCH + aLane;
    const uint32_t aLo = sb + SM_ALO + (wm * 64) * TPITCH + aLane;
    const uint32_t bHi = sb + SM_WHI + (wn * 32) * TPITCH + bLane;
    const uint32_t bLo = sb + SM_WLO + (wn * 32) * TPITCH + bLane;

    const float* bias_s = reinterpret_cast<const float*>(smem + SM_BIAS);
    float* stg = reinterpret_cast<float*>(smem + SM_STAGE);
    const int cb = wn * 32 + (lane & 3) * 2;     /* this thread's base col */
    float bia0[4], bia1[4];
    /* (bias smem ready only after first __syncthreads below; load there) */

    for (int im = 0; im < M_ITERS; im++) {
        const int m_base = (blockIdx.x * M_ITERS + im) * BM;

        load_tile_async(sb + SM_AHI, g_Ahi + ((size_t)t * MM + m_base) * KK, tid);
        load_tile_async(sb + SM_ALO, g_Alo + ((size_t)t * MM + m_base) * KK, tid);
        cp_wait_all();
        __syncthreads();

        if (im == 0) {
            #pragma unroll
            for (int nj = 0; nj < 4; nj++) {
                bia0[nj] = bias_s[cb + nj * 8];
                bia1[nj] = bias_s[cb + nj * 8 + 1];
            }
        }

        float acc[4][4][4];
        #pragma unroll
        for (int mi = 0; mi < 4; mi++)
            #pragma unroll
            for (int nj = 0; nj < 4; nj++)
                #pragma unroll
                for (int q = 0; q < 4; q++) acc[mi][nj][q] = 0.0f;

        /* 3 passes: Ahi*Whi + Ahi*Wlo + Alo*Whi */
        #pragma unroll
        for (int p = 0; p < 3; p++) {
            const uint32_t aB = (p == 2) ? aLo : aHi;
            const uint32_t bB = (p == 1) ? bLo : bHi;
            #pragma unroll
            for (int ks = 0; ks < 8; ks++) {
                const uint32_t kb = ks * 32;
                uint32_t bf[2][4], af[4][4];
                ldsm4(bf[0], bB + kb);
                ldsm4(bf[1], bB + 16 * TPITCH + kb);
                #pragma unroll
                for (int mi = 0; mi < 4; mi++)
                    ldsm4(af[mi], aB + mi * (16 * TPITCH) + kb);
                #pragma unroll
                for (int mi = 0; mi < 4; mi++)
                    #pragma unroll
                    for (int nj = 0; nj < 4; nj++)
                        mma16816(acc[mi][nj], af[mi], &bf[nj >> 1][(nj & 1) * 2]);
            }
        }

        __syncthreads();          /* A tiles dead; stage region reuses them */

        /* epilogue: bias + exact-erf GELU into padded fp32 stage */
        const int r0 = wm * 64 + (lane >> 2);
        #pragma unroll
        for (int mi = 0; mi < 4; mi++) {
            #pragma unroll
            for (int nj = 0; nj < 4; nj++) {
                const int col = cb + nj * 8;
                float v0 = acc[mi][nj][0] + bia0[nj];
                float v1 = acc[mi][nj][1] + bia1[nj];
                float v2 = acc[mi][nj][2] + bia0[nj];
                float v3 = acc[mi][nj][3] + bia1[nj];
                v0 = 0.5f * v0 * (1.0f + erff(v0 * 0.70710678118654752f));
                v1 = 0.5f * v1 * (1.0f + erff(v1 * 0.70710678118654752f));
                v2 = 0.5f * v2 * (1.0f + erff(v2 * 0.70710678118654752f));
                v3 = 0.5f * v3 * (1.0f + erff(v3 * 0.70710678118654752f));
                const int rA = r0 + mi * 16, rB = rA + 8;
                stg[rA * STAGE_LD + col]     = v0;
                stg[rA * STAGE_LD + col + 1] = v1;
                stg[rB * STAGE_LD + col]     = v2;
                stg[rB * STAGE_LD + col + 1] = v3;
            }
        }
        __syncthreads();

        /* fully coalesced writeout */
        float* obase = out + ((size_t)t * MM + m_base) * NN + n0;
        #pragma unroll
        for (int it = 0; it < 16; it++) {
            int e = tid + it * 256;
            int r = e >> 5, c4 = (e & 31) * 4;
            float4 v = *reinterpret_cast<const float4*>(&stg[r * STAGE_LD + c4]);
            *reinterpret_cast<float4*>(&obase[(size_t)r * NN + c4]) = v;
        }
        __syncthreads();          /* stage dead before next iter's cp.async */
    }
}

/* ============================ launch ============================ */
extern "C" void kernel_launch(void* const* d_in, const int* in_sizes, int n_in,
                              void* d_out, int out_size) {
    const float* A    = (const float*)d_in[0];   /* inputs  [8,1,16384,128] f32 */
    const float* W    = (const float*)d_in[1];   /* weights [8,1,128,1024] f32 */
    const float* bias = (const float*)d_in[2];   /* biases  [8,1,1,1024]  f32 */
    float* out = (float*)d_out;                  /* [8,1,16384,1024] f32 */

    split_A_kernel<<<(TT * MM * KK / 4) / 256, 256>>>(A);
    split_W_kernel<<<(TT * KK * NN) / 256, 256>>>(W);

    cudaFuncSetAttribute(fused_gemm_kernel,
                         cudaFuncAttributeMaxDynamicSharedMemorySize, SM_TOTAL);
    dim3 grid(MGROUPS, NN / BN, TT);
    fused_gemm_kernel<<<grid, 256, SM_TOTAL>>>(bias, out);
}

// round 4
// speedup vs baseline: 1.6094x; 1.6094x over previous
#include <cuda_runtime.h>
#include <cuda_fp16.h>
#include <cstdint>
#include <cstddef>

#define TT 8
#define MM 16384
#define KK 128
#define NN 1024

#define BM 128
#define BN 128
#define M_ITERS 8
#define MGROUPS 16          /* 16384 / 128 / 8 */

/* SMEM tiles: 128 rows x 136 fp16 (272 B pitch; pad keeps ldmatrix conflict-free) */
#define TPITCH     272
#define TILE_BYTES (128 * TPITCH)     /* 34816 */

#define SM_BIAS  0
#define SM_W     512
#define SM_A0HI  (SM_W    + TILE_BYTES)
#define SM_A0LO  (SM_A0HI + TILE_BYTES)
#define SM_A1HI  (SM_A0LO + TILE_BYTES)
#define SM_A1LO  (SM_A1HI + TILE_BYTES)
#define SM_TOTAL (SM_A1LO + TILE_BYTES)     /* 174592 B */

/* ---- scratch (alloc-free rule: __device__ globals) ---- */
__device__ __align__(16) __half g_Ahi[(size_t)TT*MM*KK];
__device__ __align__(16) __half g_Alo[(size_t)TT*MM*KK];
__device__ __align__(16) __half g_Wh [(size_t)TT*NN*KK];

/* ============================ PTX helpers ============================ */
__device__ __forceinline__ uint32_t smem_u32(const void* p) {
    uint32_t a;
    asm("{ .reg .u64 t; cvta.to.shared.u64 t, %1; cvt.u32.u64 %0, t; }" : "=r"(a) : "l"(p));
    return a;
}
__device__ __forceinline__ void cp16(uint32_t s, const void* g) {
    asm volatile("cp.async.cg.shared.global [%0], [%1], 16;" :: "r"(s), "l"(g));
}
__device__ __forceinline__ void cp_commit() {
    asm volatile("cp.async.commit_group;" ::: "memory");
}
__device__ __forceinline__ void cp_wait0() {
    asm volatile("cp.async.wait_group 0;" ::: "memory");
}
__device__ __forceinline__ void ldsm4(uint32_t* r, uint32_t addr) {
    asm volatile("ldmatrix.sync.aligned.m8n8.x4.shared.b16 {%0,%1,%2,%3}, [%4];"
                 : "=r"(r[0]), "=r"(r[1]), "=r"(r[2]), "=r"(r[3]) : "r"(addr));
}
__device__ __forceinline__ void mma16816(float* c, const uint32_t* a, const uint32_t* b) {
    asm volatile(
        "mma.sync.aligned.m16n8k16.row.col.f32.f16.f16.f32 "
        "{%0,%1,%2,%3}, {%4,%5,%6,%7}, {%8,%9}, {%0,%1,%2,%3};"
        : "+f"(c[0]), "+f"(c[1]), "+f"(c[2]), "+f"(c[3])
        : "r"(a[0]), "r"(a[1]), "r"(a[2]), "r"(a[3]), "r"(b[0]), "r"(b[1]));
}

/* ============================ split kernels ============================ */
__global__ void split_A_kernel(const float* __restrict__ A) {
    size_t i = (size_t)blockIdx.x * blockDim.x + threadIdx.x;   /* over float4s */
    float4 v = reinterpret_cast<const float4*>(A)[i];
    __half h0 = __float2half_rn(v.x), h1 = __float2half_rn(v.y);
    __half h2 = __float2half_rn(v.z), h3 = __float2half_rn(v.w);
    __half l0 = __float2half_rn(v.x - __half2float(h0));
    __half l1 = __float2half_rn(v.y - __half2float(h1));
    __half l2 = __float2half_rn(v.z - __half2float(h2));
    __half l3 = __float2half_rn(v.w - __half2float(h3));
    uint2 H, L;
    H.x = (uint32_t)__half_as_ushort(h0) | ((uint32_t)__half_as_ushort(h1) << 16);
    H.y = (uint32_t)__half_as_ushort(h2) | ((uint32_t)__half_as_ushort(h3) << 16);
    L.x = (uint32_t)__half_as_ushort(l0) | ((uint32_t)__half_as_ushort(l1) << 16);
    L.y = (uint32_t)__half_as_ushort(l2) | ((uint32_t)__half_as_ushort(l3) << 16);
    reinterpret_cast<uint2*>(g_Ahi)[i] = H;
    reinterpret_cast<uint2*>(g_Alo)[i] = L;
}

/* W [T,K,N] fp32 -> g_Wh [T,N,K] fp16 (transposed: B operand wants [N,K] K-major) */
__global__ void split_W_kernel(const float* __restrict__ W) {
    int i = blockIdx.x * blockDim.x + threadIdx.x;       /* over T*K*N, n fastest */
    int n = i % NN;
    int k = (i / NN) % KK;
    int t = i / (NN * KK);
    size_t o = ((size_t)(t * NN + n)) * KK + k;
    g_Wh[o] = __float2half_rn(W[i]);
}

/* ============================ main GEMM ============================ */
/* async-copy a 128x128 fp16 tile (gmem row stride 256 B) into padded smem rows */
__device__ __forceinline__ void load_tile_async(uint32_t sbase,
                                                const __half* __restrict__ gsrc,
                                                int tid) {
    const char* g = reinterpret_cast<const char*>(gsrc);
    #pragma unroll
    for (int it = 0; it < 8; it++) {
        int c = tid + it * 256;                 /* 2048 16B chunks */
        int row = c >> 4, cc = c & 15;
        cp16(sbase + row * TPITCH + cc * 16, g + row * 256 + cc * 16);
    }
}

__global__ void __launch_bounds__(256, 1)
fused_gemm_kernel(const float* __restrict__ biases, float* __restrict__ out) {
    extern __shared__ char smem[];
    const uint32_t sb = smem_u32(smem);
    const int tid = threadIdx.x, wid = tid >> 5, lane = tid & 31;
    const int wm = wid & 1;          /* 2 warp-rows  (64 rows each)  */
    const int wn = wid >> 1;         /* 4 warp-cols  (32 cols each)  */
    const int n0 = blockIdx.y * BN;
    const int t  = blockIdx.z;

    if (tid < BN)
        reinterpret_cast<float*>(smem + SM_BIAS)[tid] = biases[t * NN + n0 + tid];

    const __half* gA_hi = g_Ahi + ((size_t)t * MM + (size_t)blockIdx.x * M_ITERS * BM) * KK;
    const __half* gA_lo = g_Alo + ((size_t)t * MM + (size_t)blockIdx.x * M_ITERS * BM) * KK;

    /* prologue: W tile + A(0) tiles, one commit group */
    load_tile_async(sb + SM_W, g_Wh + ((size_t)(t * NN + n0)) * KK, tid);
    load_tile_async(sb + SM_A0HI, gA_hi, tid);
    load_tile_async(sb + SM_A0LO, gA_lo, tid);
    cp_commit();

    /* lane-dependent ldmatrix offsets */
    const uint32_t aLane = (uint32_t)((lane & 15) * TPITCH + ((lane & 16) ? 16 : 0));
    const uint32_t bLane = (uint32_t)(((lane & 7) + ((lane & 16) >> 1)) * TPITCH
                                      + (lane & 8) * 2);
    const uint32_t bW = sb + SM_W + (wn * 32) * TPITCH + bLane;

    const float* bias_s = reinterpret_cast<const float*>(smem + SM_BIAS);
    const int cb = wn * 32 + (lane & 3) * 2;     /* this thread's base col */
    const int r0 = wm * 64 + (lane >> 2);
    float bia0[4], bia1[4];

    for (int im = 0; im < M_ITERS; im++) {
        cp_wait0();
        __syncthreads();        /* A(im) + W ready; all warps done reading alt buf */

        if (im == 0) {
            #pragma unroll
            for (int nj = 0; nj < 4; nj++) {
                bia0[nj] = bias_s[cb + nj * 8];
                bia1[nj] = bias_s[cb + nj * 8 + 1];
            }
        }

        /* prefetch A(im+1) into the other buffer (read last in iter im-1) */
        if (im + 1 < M_ITERS) {
            const uint32_t dHi = ((im + 1) & 1) ? SM_A1HI : SM_A0HI;
            const uint32_t dLo = ((im + 1) & 1) ? SM_A1LO : SM_A0LO;
            load_tile_async(sb + dHi, gA_hi + (size_t)(im + 1) * BM * KK, tid);
            load_tile_async(sb + dLo, gA_lo + (size_t)(im + 1) * BM * KK, tid);
            cp_commit();
        }

        const uint32_t aHi = sb + ((im & 1) ? SM_A1HI : SM_A0HI)
                           + (wm * 64) * TPITCH + aLane;
        const uint32_t aLo = sb + ((im & 1) ? SM_A1LO : SM_A0LO)
                           + (wm * 64) * TPITCH + aLane;

        float acc[4][4][4];
        #pragma unroll
        for (int mi = 0; mi < 4; mi++)
            #pragma unroll
            for (int nj = 0; nj < 4; nj++)
                #pragma unroll
                for (int q = 0; q < 4; q++) acc[mi][nj][q] = 0.0f;

        /* 2 passes sharing B fragments: Ahi*W + Alo*W */
        #pragma unroll
        for (int ks = 0; ks < 8; ks++) {
            const uint32_t kb = ks * 32;
            uint32_t bf[2][4];
            ldsm4(bf[0], bW + kb);
            ldsm4(bf[1], bW + 16 * TPITCH + kb);
            uint32_t afh[4][4], afl[4][4];
            #pragma unroll
            for (int mi = 0; mi < 4; mi++) ldsm4(afh[mi], aHi + mi * (16 * TPITCH) + kb);
            #pragma unroll
            for (int mi = 0; mi < 4; mi++) ldsm4(afl[mi], aLo + mi * (16 * TPITCH) + kb);
            #pragma unroll
            for (int mi = 0; mi < 4; mi++)
                #pragma unroll
                for (int nj = 0; nj < 4; nj++) {
                    mma16816(acc[mi][nj], afh[mi], &bf[nj >> 1][(nj & 1) * 2]);
                    mma16816(acc[mi][nj], afl[mi], &bf[nj >> 1][(nj & 1) * 2]);
                }
        }

        /* epilogue: bias + exact-erf GELU, direct 8B stores (full 32B sectors) */
        const int m_base = (blockIdx.x * M_ITERS + im) * BM;
        float* obase = out + ((size_t)t * MM + m_base) * NN + n0;
        #pragma unroll
        for (int mi = 0; mi < 4; mi++) {
            #pragma unroll
            for (int nj = 0; nj < 4; nj++) {
                const int col = cb + nj * 8;
                float v0 = acc[mi][nj][0] + bia0[nj];
                float v1 = acc[mi][nj][1] + bia1[nj];
                float v2 = acc[mi][nj][2] + bia0[nj];
                float v3 = acc[mi][nj][3] + bia1[nj];
                v0 = 0.5f * v0 * (1.0f + erff(v0 * 0.70710678118654752f));
                v1 = 0.5f * v1 * (1.0f + erff(v1 * 0.70710678118654752f));
                v2 = 0.5f * v2 * (1.0f + erff(v2 * 0.70710678118654752f));
                v3 = 0.5f * v3 * (1.0f + erff(v3 * 0.70710678118654752f));
                const int rA = r0 + mi * 16, rB = rA + 8;
                float2 p0; p0.x = v0; p0.y = v1;
                float2 p1; p1.x = v2; p1.y = v3;
                *reinterpret_cast<float2*>(&obase[(size_t)rA * NN + col]) = p0;
                *reinterpret_cast<float2*>(&obase[(size_t)rB * NN + col]) = p1;
            }
        }
        /* no barrier: next iter's sync (after cp_wait0) provides the hazard guard */
    }
}

/* ============================ launch ============================ */
extern "C" void kernel_launch(void* const* d_in, const int* in_sizes, int n_in,
                              void* d_out, int out_size) {
    const float* A    = (const float*)d_in[0];   /* inputs  [8,1,16384,128] f32 */
    const float* W    = (const float*)d_in[1];   /* weights [8,1,128,1024] f32 */
    const float* bias = (const float*)d_in[2];   /* biases  [8,1,1,1024]  f32 */
    float* out = (float*)d_out;                  /* [8,1,16384,1024] f32 */

    split_A_kernel<<<(TT * MM * KK / 4) / 256, 256>>>(A);
    split_W_kernel<<<(TT * KK * NN) / 256, 256>>>(W);

    cudaFuncSetAttribute(fused_gemm_kernel,
                         cudaFuncAttributeMaxDynamicSharedMemorySize, SM_TOTAL);
    dim3 grid(MGROUPS, NN / BN, TT);
    fused_gemm_kernel<<<grid, 256, SM_TOTAL>>>(bias, out);
}

// round 5
// speedup vs baseline: 2.8134x; 1.7481x over previous
#include <cuda_runtime.h>
#include <cuda_fp16.h>
#include <cstdint>
#include <cstddef>

#define TT 8
#define MM 16384
#define KK 128
#define NN 1024

#define BM 128
#define BN 128
#define M_ITERS 8
#define MGROUPS 16          /* 16384 / 128 / 8 */

/* SMEM tiles: 128 rows x 136 fp16 (272 B pitch; pad keeps ldmatrix conflict-free) */
#define TPITCH     272
#define TILE_BYTES (128 * TPITCH)     /* 34816 */

#define SM_BIAS  0
#define SM_W     512
#define SM_A0    (SM_W  + TILE_BYTES)
#define SM_A1    (SM_A0 + TILE_BYTES)
#define SM_TOTAL (SM_A1 + TILE_BYTES)      /* 104960 B -> 2 CTAs/SM */

/* ---- scratch (alloc-free rule: __device__ globals) ---- */
__device__ __align__(16) __half g_Ah[(size_t)TT*MM*KK];
__device__ __align__(16) __half g_Wh[(size_t)TT*NN*KK];

/* ============================ PTX helpers ============================ */
__device__ __forceinline__ uint32_t smem_u32(const void* p) {
    uint32_t a;
    asm("{ .reg .u64 t; cvta.to.shared.u64 t, %1; cvt.u32.u64 %0, t; }" : "=r"(a) : "l"(p));
    return a;
}
__device__ __forceinline__ void cp16(uint32_t s, const void* g) {
    asm volatile("cp.async.cg.shared.global [%0], [%1], 16;" :: "r"(s), "l"(g));
}
__device__ __forceinline__ void cp_commit() {
    asm volatile("cp.async.commit_group;" ::: "memory");
}
__device__ __forceinline__ void cp_wait0() {
    asm volatile("cp.async.wait_group 0;" ::: "memory");
}
__device__ __forceinline__ void ldsm4(uint32_t* r, uint32_t addr) {
    asm volatile("ldmatrix.sync.aligned.m8n8.x4.shared.b16 {%0,%1,%2,%3}, [%4];"
                 : "=r"(r[0]), "=r"(r[1]), "=r"(r[2]), "=r"(r[3]) : "r"(addr));
}
__device__ __forceinline__ void mma16816(float* c, const uint32_t* a, const uint32_t* b) {
    asm volatile(
        "mma.sync.aligned.m16n8k16.row.col.f32.f16.f16.f32 "
        "{%0,%1,%2,%3}, {%4,%5,%6,%7}, {%8,%9}, {%0,%1,%2,%3};"
        : "+f"(c[0]), "+f"(c[1]), "+f"(c[2]), "+f"(c[3])
        : "r"(a[0]), "r"(a[1]), "r"(a[2]), "r"(a[3]), "r"(b[0]), "r"(b[1]));
}

/* ---- exact-form GELU, zero MUFU, zero branches ----
 * erf(z) = 1 - (1 + a1 z + ... + a6 z^6)^-16  (A&S 7.1.28, |eps|<=3e-7)
 * reciprocal via int-magic seed + 3 FMA Newton steps.                     */
__device__ __forceinline__ float gelu_exact(float v) {
    float z  = 0.70710678118654752f * v;
    float az = fminf(fabsf(z), 3.9f);            /* erf(3.9)=1-1e-7; avoids inf */
    float w  = 0.0000430638f;
    w = fmaf(w, az, 0.0002765672f);
    w = fmaf(w, az, 0.0001520143f);
    w = fmaf(w, az, 0.0092705272f);
    w = fmaf(w, az, 0.0422820123f);
    w = fmaf(w, az, 0.0705230784f);
    w = fmaf(w, az, 1.0f);
    float w2 = w * w, w4 = w2 * w2, w8 = w4 * w4;
    float y  = w8 * w8;                          /* w^16 in [1, ~4e7] */
    float r  = __int_as_float(0x7EF311C3 - __float_as_int(y));   /* ~1/y seed */
    r = r * fmaf(-y, r, 2.0f);
    r = r * fmaf(-y, r, 2.0f);
    r = r * fmaf(-y, r, 2.0f);                   /* rel err ~4e-8 */
    float h   = 0.5f * r;                        /* = 0.5*(1-erf(|z|)) */
    float phi = (v >= 0.0f) ? (1.0f - h) : h;    /* Phi(v) */
    return v * phi;
}

/* ============================ convert kernels ============================ */
__global__ void conv_A_kernel(const float* __restrict__ A) {
    size_t i = (size_t)blockIdx.x * blockDim.x + threadIdx.x;   /* over float4s */
    float4 v = reinterpret_cast<const float4*>(A)[i];
    __half h0 = __float2half_rn(v.x), h1 = __float2half_rn(v.y);
    __half h2 = __float2half_rn(v.z), h3 = __float2half_rn(v.w);
    uint2 H;
    H.x = (uint32_t)__half_as_ushort(h0) | ((uint32_t)__half_as_ushort(h1) << 16);
    H.y = (uint32_t)__half_as_ushort(h2) | ((uint32_t)__half_as_ushort(h3) << 16);
    reinterpret_cast<uint2*>(g_Ah)[i] = H;
}

/* W [T,K,N] fp32 -> g_Wh [T,N,K] fp16 (transposed: B operand wants [N,K] K-major) */
__global__ void conv_W_kernel(const float* __restrict__ W) {
    int i = blockIdx.x * blockDim.x + threadIdx.x;       /* over T*K*N, n fastest */
    int n = i % NN;
    int k = (i / NN) % KK;
    int t = i / (NN * KK);
    size_t o = ((size_t)(t * NN + n)) * KK + k;
    g_Wh[o] = __float2half_rn(W[i]);
}

/* ============================ main GEMM ============================ */
/* async-copy a 128x128 fp16 tile (gmem row stride 256 B) into padded smem rows */
__device__ __forceinline__ void load_tile_async(uint32_t sbase,
                                                const __half* __restrict__ gsrc,
                                                int tid) {
    const char* g = reinterpret_cast<const char*>(gsrc);
    #pragma unroll
    for (int it = 0; it < 8; it++) {
        int c = tid + it * 256;                 /* 2048 16B chunks */
        int row = c >> 4, cc = c & 15;
        cp16(sbase + row * TPITCH + cc * 16, g + row * 256 + cc * 16);
    }
}

__global__ void __launch_bounds__(256, 2)
fused_gemm_kernel(const float* __restrict__ biases, float* __restrict__ out) {
    extern __shared__ char smem[];
    const uint32_t sb = smem_u32(smem);
    const int tid = threadIdx.x, wid = tid >> 5, lane = tid & 31;
    const int wm = wid & 1;          /* 2 warp-rows  (64 rows each)  */
    const int wn = wid >> 1;         /* 4 warp-cols  (32 cols each)  */
    const int n0 = blockIdx.y * BN;
    const int t  = blockIdx.z;

    if (tid < BN)
        reinterpret_cast<float*>(smem + SM_BIAS)[tid] = biases[t * NN + n0 + tid];

    const __half* gA = g_Ah + ((size_t)t * MM + (size_t)blockIdx.x * M_ITERS * BM) * KK;

    /* prologue: W tile + A(0) tile, one commit group */
    load_tile_async(sb + SM_W,  g_Wh + ((size_t)(t * NN + n0)) * KK, tid);
    load_tile_async(sb + SM_A0, gA, tid);
    cp_commit();

    /* lane-dependent ldmatrix offsets */
    const uint32_t aLane = (uint32_t)((lane & 15) * TPITCH + ((lane & 16) ? 16 : 0));
    const uint32_t bLane = (uint32_t)(((lane & 7) + ((lane & 16) >> 1)) * TPITCH
                                      + (lane & 8) * 2);
    const uint32_t bW = sb + SM_W + (wn * 32) * TPITCH + bLane;

    const float* bias_s = reinterpret_cast<const float*>(smem + SM_BIAS);
    const int cb = wn * 32 + (lane & 3) * 2;     /* this thread's base col */
    const int r0 = wm * 64 + (lane >> 2);
    float bia0[4], bia1[4];

    for (int im = 0; im < M_ITERS; im++) {
        cp_wait0();
        __syncthreads();        /* A(im) + W ready; all warps done reading alt buf */

        if (im == 0) {
            #pragma unroll
            for (int nj = 0; nj < 4; nj++) {
                bia0[nj] = bias_s[cb + nj * 8];
                bia1[nj] = bias_s[cb + nj * 8 + 1];
            }
        }

        /* prefetch A(im+1) into the other buffer (last read in iter im-1) */
        if (im + 1 < M_ITERS) {
            const uint32_t d = ((im + 1) & 1) ? SM_A1 : SM_A0;
            load_tile_async(sb + d, gA + (size_t)(im + 1) * BM * KK, tid);
            cp_commit();
        }

        const uint32_t aC = sb + ((im & 1) ? SM_A1 : SM_A0)
                          + (wm * 64) * TPITCH + aLane;

        float acc[4][4][4];
        #pragma unroll
        for (int mi = 0; mi < 4; mi++)
            #pragma unroll
            for (int nj = 0; nj < 4; nj++)
                #pragma unroll
                for (int q = 0; q < 4; q++) acc[mi][nj][q] = 0.0f;

        #pragma unroll
        for (int ks = 0; ks < 8; ks++) {
            const uint32_t kb = ks * 32;
            uint32_t bf[2][4];
            ldsm4(bf[0], bW + kb);
            ldsm4(bf[1], bW + 16 * TPITCH + kb);
            uint32_t af[4][4];
            #pragma unroll
            for (int mi = 0; mi < 4; mi++) ldsm4(af[mi], aC + mi * (16 * TPITCH) + kb);
            #pragma unroll
            for (int mi = 0; mi < 4; mi++)
                #pragma unroll
                for (int nj = 0; nj < 4; nj++)
                    mma16816(acc[mi][nj], af[mi], &bf[nj >> 1][(nj & 1) * 2]);
        }

        /* epilogue: bias + FMA-only exact GELU, direct 8B stores */
        const int m_base = (blockIdx.x * M_ITERS + im) * BM;
        float* obase = out + ((size_t)t * MM + m_base) * NN + n0;
        #pragma unroll
        for (int mi = 0; mi < 4; mi++) {
            #pragma unroll
            for (int nj = 0; nj < 4; nj++) {
                const int col = cb + nj * 8;
                float2 p0, p1;
                p0.x = gelu_exact(acc[mi][nj][0] + bia0[nj]);
                p0.y = gelu_exact(acc[mi][nj][1] + bia1[nj]);
                p1.x = gelu_exact(acc[mi][nj][2] + bia0[nj]);
                p1.y = gelu_exact(acc[mi][nj][3] + bia1[nj]);
                const int rA = r0 + mi * 16, rB = rA + 8;
                *reinterpret_cast<float2*>(&obase[(size_t)rA * NN + col]) = p0;
                *reinterpret_cast<float2*>(&obase[(size_t)rB * NN + col]) = p1;
            }
        }
        /* no barrier: next iter's sync (after cp_wait0) provides the hazard guard */
    }
}

/* ============================ launch ============================ */
extern "C" void kernel_launch(void* const* d_in, const int* in_sizes, int n_in,
                              void* d_out, int out_size) {
    const float* A    = (const float*)d_in[0];   /* inputs  [8,1,16384,128] f32 */
    const float* W    = (const float*)d_in[1];   /* weights [8,1,128,1024] f32 */
    const float* bias = (const float*)d_in[2];   /* biases  [8,1,1,1024]  f32 */
    float* out = (float*)d_out;                  /* [8,1,16384,1024] f32 */

    conv_A_kernel<<<(TT * MM * KK / 4) / 256, 256>>>(A);
    conv_W_kernel<<<(TT * KK * NN) / 256, 256>>>(W);

    cudaFuncSetAttribute(fused_gemm_kernel,
                         cudaFuncAttributeMaxDynamicSharedMemorySize, SM_TOTAL);
    dim3 grid(MGROUPS, NN / BN, TT);
    fused_gemm_kernel<<<grid, 256, SM_TOTAL>>>(bias, out);
}